// round 3
// baseline (speedup 1.0000x reference)
#include <cuda_runtime.h>
#include <cuda_bf16.h>
#include <cstddef>

// CompressK: ragged strided chunk mean-pool.
//   k:          [total_tokens, H, D] fp32   (H*D = 512 for this problem)
//   cu_seqlens: [B+1] int32
//   kernel_size, kernel_stride: int32 scalars (device)
// Output: compressed_k [NC, H, D] fp32, optionally followed by the (B+1)
// compressed cu_seqlens written as float values.

#define HD    512          // H * D (4 * 128) — fixed for this problem instance
#define HD4   (HD / 4)     // float4 lanes per row

__global__ void compressk_mean_kernel(const float4* __restrict__ k4,
                                      const int*    __restrict__ cu,
                                      const int*    __restrict__ p_ks,
                                      const int*    __restrict__ p_st,
                                      float4*       __restrict__ out4,
                                      int B)
{
    const int c   = blockIdx.x;      // chunk id
    const int tid = threadIdx.x;     // 0..HD4-1
    const int ks  = __ldg(p_ks);
    const int st  = __ldg(p_st);

    // Map chunk id -> starting token via a scan over the (tiny) cu_seqlens.
    int acc = 0;
    int start_tok = 0;
    #pragma unroll 4
    for (int i = 0; i < B; i++) {
        const int s0  = __ldg(cu + i);
        const int s1  = __ldg(cu + i + 1);
        const int len = s1 - s0;
        const int nc  = (len >= ks) ? (len - ks) / st + 1 : 0;
        if (c >= acc && c < acc + nc) {
            start_tok = s0 + (c - acc) * st;
        }
        acc += nc;
    }

    const float4* row = k4 + (size_t)start_tok * HD4 + tid;

    float4 s = make_float4(0.f, 0.f, 0.f, 0.f);
    #pragma unroll 8
    for (int t = 0; t < ks; t++) {
        const float4 v = row[(size_t)t * HD4];
        s.x += v.x; s.y += v.y; s.z += v.z; s.w += v.w;
    }

    const float inv = 1.0f / (float)ks;
    s.x *= inv; s.y *= inv; s.z *= inv; s.w *= inv;

    out4[(size_t)c * HD4 + tid] = s;
}

// Writes the compressed cu_seqlens (as float values) into the tail of d_out,
// if the harness expects it concatenated after compressed_k.
__global__ void compressk_tail_kernel(const int* __restrict__ cu,
                                      const int* __restrict__ p_ks,
                                      const int* __restrict__ p_st,
                                      float*     __restrict__ out_tail,
                                      int B)
{
    const int i = threadIdx.x;       // 0..B
    if (i > B) return;
    const int ks = __ldg(p_ks);
    const int st = __ldg(p_st);
    int acc = 0;
    for (int j = 0; j < i; j++) {
        const int len = __ldg(cu + j + 1) - __ldg(cu + j);
        acc += (len >= ks) ? (len - ks) / st + 1 : 0;
    }
    out_tail[i] = (float)acc;
}

extern "C" void kernel_launch(void* const* d_in, const int* in_sizes, int n_in,
                              void* d_out, int out_size)
{
    const float4* k4   = (const float4*)d_in[0];
    const int*    cu   = (const int*)d_in[1];
    const int*    p_ks = (const int*)d_in[2];
    const int*    p_st = (const int*)d_in[3];

    const int B = in_sizes[1] - 1;

    // Number of chunks from the output size; any remainder beyond full
    // [NC, H, D] rows is the appended compressed cu_seqlens.
    const int NC   = out_size / HD;
    const int tail = out_size - NC * HD;

    if (NC > 0) {
        compressk_mean_kernel<<<NC, HD4>>>(k4, cu, p_ks, p_st,
                                           (float4*)d_out, B);
    }
    if (tail > 0) {
        compressk_tail_kernel<<<1, tail>>>(cu, p_ks, p_st,
                                           (float*)d_out + (size_t)NC * HD,
                                           B);
    }
}

// round 4
// speedup vs baseline: 1.1575x; 1.1575x over previous
#include <cuda_runtime.h>
#include <cuda_bf16.h>
#include <cstddef>

// CompressK: ragged strided chunk mean-pool (NSA K compression).
//   k:          [total_tokens, H, D] fp32   (H*D = 512 here)
//   cu_seqlens: [B+1] int32
//   kernel_size, kernel_stride: int32 scalars (device)
// Output: compressed_k [NC, H, D] fp32 followed by (B+1) compressed
// cu_seqlens written as float values.
//
// Optimization: with ks == 2*st, chunk c = halfsum(c) + halfsum(c+1).
// A block processes G consecutive chunks of one sequence, streaming the
// half-sums through registers: reads G+1 halves, writes G chunks.
// Traffic: 2*NC halves (naive) -> NC + NC/G halves.

#define HD    512          // H * D
#define HD4   (HD / 4)     // float4 lanes per row (= block size)
#define G     4            // chunks per block (fast path)

__global__ void __launch_bounds__(HD4)
compressk_group_kernel(const float4* __restrict__ k4,
                       const int*    __restrict__ cu,
                       const int*    __restrict__ p_ks,
                       const int*    __restrict__ p_st,
                       float4*       __restrict__ out4,
                       float*        __restrict__ out_tail,
                       int B, int tail_n)
{
    const int tid = threadIdx.x;
    const int g   = blockIdx.x;
    const int ks  = __ldg(p_ks);
    const int st  = __ldg(p_st);

    // Fused tail: block 0 writes the compressed cu_seqlens.
    if (g == 0 && tid < tail_n) {
        int acc = 0;
        for (int j = 0; j < tid; j++) {
            const int len = __ldg(cu + j + 1) - __ldg(cu + j);
            acc += (len >= ks) ? (len - ks) / st + 1 : 0;
        }
        out_tail[tid] = (float)acc;
    }

    // Locate this block's chunk group: scan the (tiny) cu_seqlens.
    int start_tok = 0;     // first token of first chunk in group
    int chunk0    = 0;     // global chunk index of first chunk in group
    int gn        = 0;     // number of chunks in this group
    {
        int gacc = 0;      // groups so far
        int cacc = 0;      // chunks so far
        #pragma unroll 4
        for (int i = 0; i < B; i++) {
            const int s0  = __ldg(cu + i);
            const int s1  = __ldg(cu + i + 1);
            const int len = s1 - s0;
            const int nc  = (len >= ks) ? (len - ks) / st + 1 : 0;
            const int ng  = (nc + G - 1) / G;
            if (g >= gacc && g < gacc + ng) {
                const int gi = g - gacc;       // group index within seq
                const int c0 = gi * G;         // chunk index within seq
                gn        = min(G, nc - c0);
                chunk0    = cacc + c0;
                start_tok = s0 + c0 * st;
            }
            gacc += ng;
            cacc += nc;
        }
    }
    if (gn <= 0) return;

    const float inv = 1.0f / (float)ks;

    if (ks == 2 * st) {
        // ── Fast path: streaming half-sums ──────────────────────────────
        const float4* p = k4 + (size_t)start_tok * HD4 + tid;
        const size_t rowstep = HD4;

        // prev = sum of first st rows
        float4 prev = make_float4(0.f, 0.f, 0.f, 0.f);
        #pragma unroll 16
        for (int t = 0; t < st; t++) {
            const float4 v = p[(size_t)t * rowstep];
            prev.x += v.x; prev.y += v.y; prev.z += v.z; prev.w += v.w;
        }
        p += (size_t)st * rowstep;

        for (int h = 0; h < gn; h++) {
            float4 cur = make_float4(0.f, 0.f, 0.f, 0.f);
            #pragma unroll 16
            for (int t = 0; t < st; t++) {
                const float4 v = p[(size_t)t * rowstep];
                cur.x += v.x; cur.y += v.y; cur.z += v.z; cur.w += v.w;
            }
            p += (size_t)st * rowstep;

            float4 o;
            o.x = (prev.x + cur.x) * inv;
            o.y = (prev.y + cur.y) * inv;
            o.z = (prev.z + cur.z) * inv;
            o.w = (prev.w + cur.w) * inv;
            out4[(size_t)(chunk0 + h) * HD4 + tid] = o;
            prev = cur;
        }
    } else {
        // ── Generic fallback: naive per-chunk sum ───────────────────────
        for (int h = 0; h < gn; h++) {
            const float4* p = k4 + (size_t)(start_tok + h * st) * HD4 + tid;
            float4 s = make_float4(0.f, 0.f, 0.f, 0.f);
            #pragma unroll 8
            for (int t = 0; t < ks; t++) {
                const float4 v = p[(size_t)t * HD4];
                s.x += v.x; s.y += v.y; s.z += v.z; s.w += v.w;
            }
            s.x *= inv; s.y *= inv; s.z *= inv; s.w *= inv;
            out4[(size_t)(chunk0 + h) * HD4 + tid] = s;
        }
    }
}

extern "C" void kernel_launch(void* const* d_in, const int* in_sizes, int n_in,
                              void* d_out, int out_size)
{
    const float4* k4   = (const float4*)d_in[0];
    const int*    cu   = (const int*)d_in[1];
    const int*    p_ks = (const int*)d_in[2];
    const int*    p_st = (const int*)d_in[3];

    const int B = in_sizes[1] - 1;

    // Chunk count from output size; remainder = appended compressed cu_seqlens.
    const int NC   = out_size / HD;
    const int tail = out_size - NC * HD;

    if (NC <= 0) return;

    // Upper bound on groups: ceil(NC/G) plus one partial group per sequence.
    const int max_groups = (NC + G - 1) / G + B;

    compressk_group_kernel<<<max_groups, HD4>>>(
        k4, cu, p_ks, p_st,
        (float4*)d_out,
        (float*)d_out + (size_t)NC * HD,
        B, tail);
}

// round 6
// speedup vs baseline: 1.3821x; 1.1940x over previous
#include <cuda_runtime.h>
#include <cuda_bf16.h>
#include <cstddef>

// CompressK: ragged strided chunk mean-pool (NSA K compression).
//   k:          [total_tokens, H, D] fp32   (H*D = 512 here)
//   cu_seqlens: [B+1] int32
//   kernel_size, kernel_stride: int32 scalars (device)
// Output: compressed_k [NC, H, D] fp32 followed by (B+1) compressed
// cu_seqlens written as float values.
//
// R4: G=2 chunk grouping (half-sum register sharing, 1.5x halves traffic)
// with ~2x the CTA count of R3, plus explicit 16-deep load batching to
// force MLP=16 per thread. Fast path compile-time specialized to
// ks=32/st=16; generic fallback for other metadata.

#define HD    512          // H * D
#define HD4   (HD / 4)     // float4 lanes per row (= block size)
#define G     2            // chunks per block (fast path)
#define KS_C  32
#define ST_C  16

__device__ __forceinline__ float4 halfsum16(const float4* __restrict__ p)
{
    float4 v[ST_C];
    #pragma unroll
    for (int t = 0; t < ST_C; t++) v[t] = p[(size_t)t * HD4];

    float4 s = make_float4(0.f, 0.f, 0.f, 0.f);
    #pragma unroll
    for (int t = 0; t < ST_C; t++) {
        s.x += v[t].x; s.y += v[t].y; s.z += v[t].z; s.w += v[t].w;
    }
    return s;
}

__global__ void __launch_bounds__(HD4)
compressk_group_kernel(const float4* __restrict__ k4,
                       const int*    __restrict__ cu,
                       const int*    __restrict__ p_ks,
                       const int*    __restrict__ p_st,
                       float4*       __restrict__ out4,
                       float*        __restrict__ out_tail,
                       int B, int tail_n)
{
    const int tid = threadIdx.x;
    const int g   = blockIdx.x;
    const int ks  = __ldg(p_ks);
    const int st  = __ldg(p_st);

    // Fused tail: block 0 writes the compressed cu_seqlens.
    if (g == 0 && tid < tail_n) {
        int acc = 0;
        for (int j = 0; j < tid; j++) {
            const int len = __ldg(cu + j + 1) - __ldg(cu + j);
            acc += (len >= ks) ? (len - ks) / st + 1 : 0;
        }
        out_tail[tid] = (float)acc;
    }

    // Locate this block's chunk group: scan the (tiny) cu_seqlens.
    int start_tok = 0;     // first token of first chunk in group
    int chunk0    = 0;     // global chunk index of first chunk in group
    int gn        = 0;     // number of chunks in this group
    {
        int gacc = 0;      // groups so far
        int cacc = 0;      // chunks so far
        #pragma unroll 4
        for (int i = 0; i < B; i++) {
            const int s0  = __ldg(cu + i);
            const int s1  = __ldg(cu + i + 1);
            const int len = s1 - s0;
            const int nc  = (len >= ks) ? (len - ks) / st + 1 : 0;
            const int ng  = (nc + G - 1) / G;
            if (g >= gacc && g < gacc + ng) {
                const int gi = g - gacc;       // group index within seq
                const int c0 = gi * G;         // chunk index within seq
                gn        = min(G, nc - c0);
                chunk0    = cacc + c0;
                start_tok = s0 + c0 * st;
            }
            gacc += ng;
            cacc += nc;
        }
    }
    if (gn <= 0) return;

    const float inv = 1.0f / (float)ks;

    if (ks == KS_C && st == ST_C) {
        // ── Fast path: streaming half-sums with forced MLP=16 ──────────
        const float4* p = k4 + (size_t)start_tok * HD4 + tid;

        float4 prev = halfsum16(p);
        p += (size_t)ST_C * HD4;

        #pragma unroll
        for (int h = 0; h < G; h++) {
            if (h >= gn) break;
            const float4 cur = halfsum16(p);
            p += (size_t)ST_C * HD4;

            float4 o;
            o.x = (prev.x + cur.x) * inv;
            o.y = (prev.y + cur.y) * inv;
            o.z = (prev.z + cur.z) * inv;
            o.w = (prev.w + cur.w) * inv;
            out4[(size_t)(chunk0 + h) * HD4 + tid] = o;
            prev = cur;
        }
    } else {
        // ── Generic fallback: naive per-chunk sum ───────────────────────
        for (int h = 0; h < gn; h++) {
            const float4* p = k4 + (size_t)(start_tok + h * st) * HD4 + tid;
            float4 s = make_float4(0.f, 0.f, 0.f, 0.f);
            #pragma unroll 8
            for (int t = 0; t < ks; t++) {
                const float4 v = p[(size_t)t * HD4];
                s.x += v.x; s.y += v.y; s.z += v.z; s.w += v.w;
            }
            s.x *= inv; s.y *= inv; s.z *= inv; s.w *= inv;
            out4[(size_t)(chunk0 + h) * HD4 + tid] = s;
        }
    }
}

extern "C" void kernel_launch(void* const* d_in, const int* in_sizes, int n_in,
                              void* d_out, int out_size)
{
    const float4* k4   = (const float4*)d_in[0];
    const int*    cu   = (const int*)d_in[1];
    const int*    p_ks = (const int*)d_in[2];
    const int*    p_st = (const int*)d_in[3];

    const int B = in_sizes[1] - 1;

    // Chunk count from output size; remainder = appended compressed cu_seqlens.
    const int NC   = out_size / HD;
    const int tail = out_size - NC * HD;

    if (NC <= 0) return;

    // Upper bound on groups: ceil(NC/G) plus one partial group per sequence.
    const int max_groups = (NC + G - 1) / G + B;

    compressk_group_kernel<<<max_groups, HD4>>>(
        k4, cu, p_ks, p_st,
        (float4*)d_out,
        (float*)d_out + (size_t)NC * HD,
        B, tail);
}